// round 12
// baseline (speedup 1.0000x reference)
#include <cuda_runtime.h>
#include <cstddef>
#include <cstdint>

#define BB 16384
#define GG 128
#define SS 64
#define HH 10
#define PHH 100

// 8MB scratch for gene_layer, stored TRANSPOSED: glT[g][b]
__device__ float g_glT[GG * BB];

// packed fp32x2 FMA (Blackwell; inline PTX only)
__device__ __forceinline__ unsigned long long f2fma(unsigned long long a,
                                                    unsigned long long b,
                                                    unsigned long long c) {
    unsigned long long d;
    asm("fma.rn.f32x2 %0, %1, %2, %3;" : "=l"(d) : "l"(a), "l"(b), "l"(c));
    return d;
}
__device__ __forceinline__ float f2lo(unsigned long long a) {
    return __uint_as_float((unsigned)a);
}
__device__ __forceinline__ float f2hi(unsigned long long a) {
    return __uint_as_float((unsigned)(a >> 32));
}
__device__ __forceinline__ unsigned long long f2dup(float v) {
    unsigned long long d;
    asm("mov.b64 %0, {%1, %1};" : "=l"(d) : "f"(v));
    return d;
}
__device__ __forceinline__ uint32_t smem_u32(const void* p) {
    uint32_t a;
    asm("{ .reg .u64 t; cvta.to.shared.u64 t, %1; cvt.u32.u64 %0, t; }"
        : "=r"(a) : "l"(p));
    return a;
}
__device__ __forceinline__ void cpasync16(uint32_t dst, const void* src) {
    asm volatile("cp.async.cg.shared.global [%0], [%1], 16;"
                 :: "r"(dst), "l"(src));
}
#define CP_COMMIT() asm volatile("cp.async.commit_group;" ::: "memory")
#define CP_WAIT(n)  asm volatile("cp.async.wait_group %0;" :: "n"(n) : "memory")

extern __shared__ unsigned char dynsmem[];

// ---------------------------------------------------------------------------
// Kernel A: gene_layer[b,g] = W2 . relu(x[b,g,:] @ W1[g] + b1) + b2
// Block = (gene, 512-row tile), 128 threads. PER-WARP 3-DEEP PIPELINES:
// each warp owns 128 rows + 3 ping-pong-pong cp.async buffers; CP_WAIT(2)
// keeps TWO chunks in DRAM flight during every compute period.
// No block barriers after W staging. 3 blocks/SM (224KB smem).
// ---------------------------------------------------------------------------
#define AR 512        // rows per block; 16384/512 = 32 tiles, no tail
#define ATH 128
#define WROWS 128     // rows per warp (R=4 per lane)
#define CPAD 12       // floats/row/chunk (8+4): banks 12l mod 32 conflict-free
#define NCHUNK 8      // s chunks of 8 cols
#define NBUF 3        // pipeline depth

#define A_SMEM_FLOATS (4 * NBUF * WROWS * CPAD + HH * SS + 36)
#define A_SMEM_BYTES (A_SMEM_FLOATS * 4)

// per-warp fill of one chunk into one buffer (cp.async, per-lane)
__device__ __forceinline__ void fill_chunk_w(uint32_t bufa, const float* xgw,
                                             int chunk, int lane) {
    const float* src = xgw + 8 * chunk;
#pragma unroll
    for (int i = lane; i < WROWS * 2; i += 32) {
        int r = i >> 1, cc = i & 1;
        cpasync16(bufa + (r * CPAD + 4 * cc) * 4,
                  src + (size_t)r * (GG * SS) + 4 * cc);
    }
    CP_COMMIT();
}

__global__ void __launch_bounds__(ATH, 3)
kernelA(const float* __restrict__ x, const float* __restrict__ W1,
        const float* __restrict__ b1, const float* __restrict__ W2,
        const float* __restrict__ b2, int tile_off) {
    float* xb  = (float*)dynsmem;                 // [4 warps][NBUF][WROWS*CPAD]
    float* wt  = xb + 4 * NBUF * WROWS * CPAD;    // [HH][SS]
    float* sb1 = wt + HH * SS;                    // [16]
    float* sW2 = sb1 + 16;                        // [16]
    float* sb2 = sW2 + 16;                        // [1]

    const int tid = threadIdx.x;
    const int lane = tid & 31;
    const int w = tid >> 5;
    const int g = blockIdx.x;
    const int b0 = (blockIdx.y + tile_off) * AR;

    float* myb[NBUF];
    uint32_t mya[NBUF];
#pragma unroll
    for (int i = 0; i < NBUF; i++) {
        myb[i] = xb + (w * NBUF + i) * WROWS * CPAD;
        mya[i] = smem_u32(myb[i]);
    }
    // this warp's 128-row slab of x
    const float* xgw = x + ((size_t)(b0 + w * WROWS) * GG + g) * SS;

    // prime per-warp pipeline: chunks 0,1,2
    fill_chunk_w(mya[0], xgw, 0, lane);
    fill_chunk_w(mya[1], xgw, 1, lane);
    fill_chunk_w(mya[2], xgw, 2, lane);

    // cooperative W staging
    {
        const float* W1g = W1 + (size_t)g * (SS * HH);
        for (int i = tid; i < SS * HH; i += ATH) {
            int s = i / HH, h = i - s * HH;
            wt[h * SS + s] = W1g[i];
        }
        if (tid < HH) {
            sb1[tid] = b1[g * HH + tid];
            sW2[tid] = W2[g * HH + tid];
        }
        if (tid == 0) sb2[0] = b2[g];
    }
    __syncthreads();   // ONLY block barrier: W visible to all warps

    unsigned long long a0[HH], a1[HH], a2[HH], a3[HH];
#pragma unroll
    for (int h = 0; h < HH; h++) { a0[h] = 0ull; a1[h] = 0ull; a2[h] = 0ull; a3[h] = 0ull; }

    int bi = 0;   // buffer index = c % NBUF
#pragma unroll 1
    for (int c = 0; c < NCHUNK; c++) {
        // chunk c must be complete; keep up to 2 later chunks in flight
        if (c < NCHUNK - 2)      { CP_WAIT(2); }
        else if (c == NCHUNK - 2){ CP_WAIT(1); }
        else                     { CP_WAIT(0); }
        __syncwarp();   // all lanes' copies of this chunk landed

        const float* buf = myb[bi];
#pragma unroll
        for (int qq = 0; qq < 2; qq++) {
            int q = c * 2 + qq;   // global s-quad for W indexing
            ulonglong2 xa = *(const ulonglong2*)(buf + (lane)      * CPAD + 4 * qq);
            ulonglong2 xbv = *(const ulonglong2*)(buf + (lane + 32) * CPAD + 4 * qq);
            ulonglong2 xc = *(const ulonglong2*)(buf + (lane + 64) * CPAD + 4 * qq);
            ulonglong2 xd = *(const ulonglong2*)(buf + (lane + 96) * CPAD + 4 * qq);
#pragma unroll
            for (int h = 0; h < HH; h++) {
                ulonglong2 wv = *(const ulonglong2*)(wt + h * SS + 4 * q); // bcast
                a0[h] = f2fma(xa.x,  wv.x, a0[h]);
                a1[h] = f2fma(xbv.x, wv.x, a1[h]);
                a2[h] = f2fma(xc.x,  wv.x, a2[h]);
                a3[h] = f2fma(xd.x,  wv.x, a3[h]);
                a0[h] = f2fma(xa.y,  wv.y, a0[h]);
                a1[h] = f2fma(xbv.y, wv.y, a1[h]);
                a2[h] = f2fma(xc.y,  wv.y, a2[h]);
                a3[h] = f2fma(xd.y,  wv.y, a3[h]);
            }
        }
        __syncwarp();   // warp done reading buf before its own refill

        if (c + NBUF < NCHUNK)
            fill_chunk_w(mya[bi], xgw, c + NBUF, lane);   // refill same buffer

        bi = (bi == NBUF - 1) ? 0 : bi + 1;
    }

    // epilogue: relu + H->1 projection; warp-coalesced stores
    float o0 = sb2[0], o1 = sb2[0], o2 = sb2[0], o3 = sb2[0];
#pragma unroll
    for (int h = 0; h < HH; h++) {
        float w2h = sW2[h];
        float u0 = f2lo(a0[h]) + f2hi(a0[h]) + sb1[h];
        float u1 = f2lo(a1[h]) + f2hi(a1[h]) + sb1[h];
        float u2 = f2lo(a2[h]) + f2hi(a2[h]) + sb1[h];
        float u3 = f2lo(a3[h]) + f2hi(a3[h]) + sb1[h];
        o0 = fmaf(fmaxf(u0, 0.f), w2h, o0);
        o1 = fmaf(fmaxf(u1, 0.f), w2h, o1);
        o2 = fmaf(fmaxf(u2, 0.f), w2h, o2);
        o3 = fmaf(fmaxf(u3, 0.f), w2h, o3);
    }
    float* glrow = g_glT + (size_t)g * BB + b0 + w * WROWS;
    glrow[lane]      = o0;
    glrow[lane + 32] = o1;
    glrow[lane + 64] = o2;
    glrow[lane + 96] = o3;
}

// ---------------------------------------------------------------------------
// Kernel B (best known: 25.3us): 128 blocks x 256 threads, 128 rows staged.
// Thread = rowslot(32; 4 rows) x jsub(8; 16 j). PH padded to 128.
// ---------------------------------------------------------------------------
#define B_THREADS 256
#define B_ROWSB 128
#define PHP 128
#define B_SMEM_FLOATS (GG * B_ROWSB + GG * PHP + PHP + PHP + 8 * B_ROWSB)
#define B_SMEM_BYTES (B_SMEM_FLOATS * 4)

__global__ void __launch_bounds__(B_THREADS, 1)
kernelB(const float* __restrict__ Wp1, const float* __restrict__ bp1,
        const float* __restrict__ Wp2, const float* __restrict__ bp2,
        float* __restrict__ out) {
    float* gls  = (float*)dynsmem;            // [G][128] (g-major)
    float* sWp1 = gls + GG * B_ROWSB;         // [G][128] zero-padded
    float* sbp1 = sWp1 + GG * PHP;            // [128]
    float* sWp2 = sbp1 + PHP;                 // [128]
    float* op   = sWp2 + PHP;                 // [8][128] partials

    const int tid = threadIdx.x;
    const int b0 = blockIdx.x * B_ROWSB;

#pragma unroll 4
    for (int i = tid; i < GG * (B_ROWSB / 4); i += B_THREADS) {
        int k = i & 31, g = i >> 5;
        *(float4*)(gls + g * B_ROWSB + 4 * k) =
            *(const float4*)(g_glT + (size_t)g * BB + b0 + 4 * k);
    }
#pragma unroll 4
    for (int i = tid; i < GG * PHP; i += B_THREADS) {
        int g = i >> 7, j = i & (PHP - 1);
        sWp1[i] = (j < PHH) ? Wp1[g * PHH + j] : 0.f;
    }
    if (tid < PHP) {
        sbp1[tid] = (tid < PHH) ? bp1[tid] : 0.f;
        sWp2[tid] = (tid < PHH) ? Wp2[tid] : 0.f;
    }
    __syncthreads();

    const int row  = tid & 31;
    const int jsub = tid >> 5;
    const int jb   = jsub * 16;

    unsigned long long acc[4][8];
#pragma unroll
    for (int k = 0; k < 4; k++)
#pragma unroll
        for (int c = 0; c < 8; c++) acc[k][c] = 0ull;

#pragma unroll 2
    for (int g = 0; g < GG; g++) {
        const float* gr = gls + g * B_ROWSB + row;
        unsigned long long x0 = f2dup(gr[0]);
        unsigned long long x1 = f2dup(gr[32]);
        unsigned long long x2 = f2dup(gr[64]);
        unsigned long long x3 = f2dup(gr[96]);
        const ulonglong2* wp = (const ulonglong2*)(sWp1 + g * PHP + jb);
#pragma unroll
        for (int p = 0; p < 4; p++) {
            ulonglong2 w = wp[p];
            acc[0][2 * p]     = f2fma(x0, w.x, acc[0][2 * p]);
            acc[1][2 * p]     = f2fma(x1, w.x, acc[1][2 * p]);
            acc[2][2 * p]     = f2fma(x2, w.x, acc[2][2 * p]);
            acc[3][2 * p]     = f2fma(x3, w.x, acc[3][2 * p]);
            acc[0][2 * p + 1] = f2fma(x0, w.y, acc[0][2 * p + 1]);
            acc[1][2 * p + 1] = f2fma(x1, w.y, acc[1][2 * p + 1]);
            acc[2][2 * p + 1] = f2fma(x2, w.y, acc[2][2 * p + 1]);
            acc[3][2 * p + 1] = f2fma(x3, w.y, acc[3][2 * p + 1]);
        }
    }

#pragma unroll
    for (int k = 0; k < 4; k++) {
        float o = 0.f;
#pragma unroll
        for (int c = 0; c < 8; c++) {
            int j0 = jb + 2 * c, j1 = j0 + 1;
            float p0 = fmaxf(f2lo(acc[k][c]) + sbp1[j0], 0.f);
            float p1 = fmaxf(f2hi(acc[k][c]) + sbp1[j1], 0.f);
            o = fmaf(p0, sWp2[j0], o);
            o = fmaf(p1, sWp2[j1], o);
        }
        op[jsub * B_ROWSB + row + 32 * k] = o;
    }
    __syncthreads();

    if (tid < B_ROWSB) {
        float v = bp2[0];
#pragma unroll
        for (int c = 0; c < 8; c++) v += op[c * B_ROWSB + tid];
        out[b0 + tid] = v;
    }
}

// ---------------------------------------------------------------------------
extern "C" void kernel_launch(void* const* d_in, const int* in_sizes, int n_in,
                              void* d_out, int out_size) {
    const float* x   = (const float*)d_in[0];
    const float* W1  = (const float*)d_in[1];
    const float* b1  = (const float*)d_in[2];
    const float* W2  = (const float*)d_in[3];
    const float* b2  = (const float*)d_in[4];
    const float* Wp1 = (const float*)d_in[5];
    const float* bp1 = (const float*)d_in[6];
    const float* Wp2 = (const float*)d_in[7];
    const float* bp2 = (const float*)d_in[8];
    float* out = (float*)d_out;

    cudaFuncSetAttribute(kernelA, cudaFuncAttributeMaxDynamicSharedMemorySize,
                         A_SMEM_BYTES);
    cudaFuncSetAttribute(kernelB, cudaFuncAttributeMaxDynamicSharedMemorySize,
                         B_SMEM_BYTES);

    // 4 slab launches (8 tiles each): ncu idx 5 lands on a kernelA slab
    dim3 gridA(GG, 8);
    kernelA<<<gridA, ATH, A_SMEM_BYTES>>>(x, W1, b1, W2, b2, 0);
    kernelA<<<gridA, ATH, A_SMEM_BYTES>>>(x, W1, b1, W2, b2, 8);
    kernelA<<<gridA, ATH, A_SMEM_BYTES>>>(x, W1, b1, W2, b2, 16);
    kernelA<<<gridA, ATH, A_SMEM_BYTES>>>(x, W1, b1, W2, b2, 24);

    dim3 gridB(BB / B_ROWSB);
    kernelB<<<gridB, B_THREADS, B_SMEM_BYTES>>>(Wp1, bp1, Wp2, bp2, out);
}

// round 14
// speedup vs baseline: 1.7057x; 1.7057x over previous
#include <cuda_runtime.h>
#include <cstddef>
#include <cstdint>

#define BB 16384
#define GG 128
#define SS 64
#define HH 10
#define PHH 100

// 8MB scratch for gene_layer, stored TRANSPOSED: glT[g][b]
__device__ float g_glT[GG * BB];

// packed fp32x2 FMA (Blackwell; inline PTX only)
__device__ __forceinline__ unsigned long long f2fma(unsigned long long a,
                                                    unsigned long long b,
                                                    unsigned long long c) {
    unsigned long long d;
    asm("fma.rn.f32x2 %0, %1, %2, %3;" : "=l"(d) : "l"(a), "l"(b), "l"(c));
    return d;
}
__device__ __forceinline__ float f2lo(unsigned long long a) {
    return __uint_as_float((unsigned)a);
}
__device__ __forceinline__ float f2hi(unsigned long long a) {
    return __uint_as_float((unsigned)(a >> 32));
}
__device__ __forceinline__ unsigned long long f2dup(float v) {
    unsigned long long d;
    asm("mov.b64 %0, {%1, %1};" : "=l"(d) : "f"(v));
    return d;
}
__device__ __forceinline__ uint32_t smem_u32(const void* p) {
    uint32_t a;
    asm("{ .reg .u64 t; cvta.to.shared.u64 t, %1; cvt.u32.u64 %0, t; }"
        : "=r"(a) : "l"(p));
    return a;
}
__device__ __forceinline__ void cpasync16(uint32_t dst, const void* src) {
    asm volatile("cp.async.cg.shared.global [%0], [%1], 16;"
                 :: "r"(dst), "l"(src));
}
#define CP_COMMIT() asm volatile("cp.async.commit_group;" ::: "memory")
#define CP_WAIT(n)  asm volatile("cp.async.wait_group %0;" :: "n"(n) : "memory")

extern __shared__ unsigned char dynsmem[];

// ---------------------------------------------------------------------------
// Kernel A (R9 proven-best config, single launch): 512-row tile, 128 threads,
// R=4 rows/thread, s streamed in 4 chunks of 16 cols through 2 ping-pong
// cp.async buffers (CP_WAIT(1)), block-barrier pipeline, 2 blocks/SM.
// ---------------------------------------------------------------------------
#define AR 512        // rows per block; 16384/512 = 32 tiles, no tail
#define ATH 128
#define CPAD 20       // floats/row/chunk (16+4): 16B pitch; banks 20i mod 32 ok
#define NCHUNK 4      // s chunks of 16

#define A_SMEM_FLOATS (2 * AR * CPAD + HH * SS + 36)
#define A_SMEM_BYTES (A_SMEM_FLOATS * 4)

__device__ __forceinline__ void fill_chunk(uint32_t bufa, const float* xg,
                                           int chunk, int tid) {
    const float* src = xg + 16 * chunk;
#pragma unroll 4
    for (int i = tid; i < AR * 4; i += ATH) {
        int r = i >> 2, cc = i & 3;
        cpasync16(bufa + (r * CPAD + 4 * cc) * 4,
                  src + (size_t)r * (GG * SS) + 4 * cc);
    }
    CP_COMMIT();
}

__global__ void __launch_bounds__(ATH, 2)
kernelA(const float* __restrict__ x, const float* __restrict__ W1,
        const float* __restrict__ b1, const float* __restrict__ W2,
        const float* __restrict__ b2) {
    float* xb0 = (float*)dynsmem;        // [AR][CPAD] buffer 0
    float* xb1 = xb0 + AR * CPAD;        // [AR][CPAD] buffer 1
    float* wt  = xb1 + AR * CPAD;        // [HH][SS]  wt[h][s]
    float* sb1 = wt + HH * SS;           // [16]
    float* sW2 = sb1 + 16;               // [16]
    float* sb2 = sW2 + 16;               // [1]

    const int tid = threadIdx.x;
    const int g = blockIdx.x;
    const int b0 = blockIdx.y * AR;

    const uint32_t ba[2] = { smem_u32(xb0), smem_u32(xb1) };
    float* const bpq[2] = { xb0, xb1 };
    const float* xg = x + ((size_t)b0 * GG + g) * SS;

    // prime pipeline: chunks 0,1
    fill_chunk(ba[0], xg, 0, tid);
    fill_chunk(ba[1], xg, 1, tid);

    // stage W while x streams
    {
        const float* W1g = W1 + (size_t)g * (SS * HH);
        for (int i = tid; i < SS * HH; i += ATH) {
            int s = i / HH, h = i - s * HH;
            wt[h * SS + s] = W1g[i];
        }
        if (tid < HH) {
            sb1[tid] = b1[g * HH + tid];
            sW2[tid] = W2[g * HH + tid];
        }
        if (tid == 0) sb2[0] = b2[g];
    }

    unsigned long long a0[HH], a1[HH], a2[HH], a3[HH];
#pragma unroll
    for (int h = 0; h < HH; h++) { a0[h] = 0ull; a1[h] = 0ull; a2[h] = 0ull; a3[h] = 0ull; }

#pragma unroll 1
    for (int c = 0; c < NCHUNK; c++) {
        if (c < NCHUNK - 1) { CP_WAIT(1); } else { CP_WAIT(0); }
        __syncthreads();

        const float* buf = bpq[c & 1];
#pragma unroll
        for (int qq = 0; qq < 4; qq++) {
            int q = c * 4 + qq;   // global quad for W indexing
            ulonglong2 xa = *(const ulonglong2*)(buf + (tid)       * CPAD + 4 * qq);
            ulonglong2 xbv = *(const ulonglong2*)(buf + (tid + 128) * CPAD + 4 * qq);
            ulonglong2 xc = *(const ulonglong2*)(buf + (tid + 256) * CPAD + 4 * qq);
            ulonglong2 xd = *(const ulonglong2*)(buf + (tid + 384) * CPAD + 4 * qq);
#pragma unroll
            for (int h = 0; h < HH; h++) {
                ulonglong2 w = *(const ulonglong2*)(wt + h * SS + 4 * q); // bcast
                a0[h] = f2fma(xa.x,  w.x, a0[h]);
                a1[h] = f2fma(xbv.x, w.x, a1[h]);
                a2[h] = f2fma(xc.x,  w.x, a2[h]);
                a3[h] = f2fma(xd.x,  w.x, a3[h]);
                a0[h] = f2fma(xa.y,  w.y, a0[h]);
                a1[h] = f2fma(xbv.y, w.y, a1[h]);
                a2[h] = f2fma(xc.y,  w.y, a2[h]);
                a3[h] = f2fma(xd.y,  w.y, a3[h]);
            }
        }
        __syncthreads();   // all done reading buf before refill

        if (c + 2 < NCHUNK)
            fill_chunk(ba[c & 1], xg, c + 2, tid);
    }

    // epilogue: relu + H->1 projection, coalesced store
    float o0 = sb2[0], o1 = sb2[0], o2 = sb2[0], o3 = sb2[0];
#pragma unroll
    for (int h = 0; h < HH; h++) {
        float w2h = sW2[h];
        float u0 = f2lo(a0[h]) + f2hi(a0[h]) + sb1[h];
        float u1 = f2lo(a1[h]) + f2hi(a1[h]) + sb1[h];
        float u2 = f2lo(a2[h]) + f2hi(a2[h]) + sb1[h];
        float u3 = f2lo(a3[h]) + f2hi(a3[h]) + sb1[h];
        o0 = fmaf(fmaxf(u0, 0.f), w2h, o0);
        o1 = fmaf(fmaxf(u1, 0.f), w2h, o1);
        o2 = fmaf(fmaxf(u2, 0.f), w2h, o2);
        o3 = fmaf(fmaxf(u3, 0.f), w2h, o3);
    }
    float* glrow = g_glT + (size_t)g * BB + b0;
    glrow[tid]       = o0;
    glrow[tid + 128] = o1;
    glrow[tid + 256] = o2;
    glrow[tid + 384] = o3;
}

// ---------------------------------------------------------------------------
// Kernel B: out[b] = relu(gl[b,:] @ Wp1 + bp1) @ Wp2 + bp2
// 256 blocks x 256 threads, 64-row tiles, gls+Wp1 staged, ~99KB smem ->
// 2 blocks/SM (16 warps). Thread = rowslot(32; rows r,r+32) x jsub(8; 16 j).
// ---------------------------------------------------------------------------
#define B_THREADS 256
#define B_ROWSB 64
#define PHP 128
#define B_SMEM_FLOATS (GG * B_ROWSB + GG * PHP + PHP + PHP + 8 * B_ROWSB)
#define B_SMEM_BYTES (B_SMEM_FLOATS * 4)

__global__ void __launch_bounds__(B_THREADS, 2)
kernelB(const float* __restrict__ Wp1, const float* __restrict__ bp1,
        const float* __restrict__ Wp2, const float* __restrict__ bp2,
        float* __restrict__ out) {
    float* gls  = (float*)dynsmem;            // [G][64] (g-major)
    float* sWp1 = gls + GG * B_ROWSB;         // [G][128] zero-padded
    float* sbp1 = sWp1 + GG * PHP;            // [128]
    float* sWp2 = sbp1 + PHP;                 // [128]
    float* op   = sWp2 + PHP;                 // [8][64] partials

    const int tid = threadIdx.x;
    const int b0 = blockIdx.x * B_ROWSB;

    // stage gene_layer tile (vectorized, coalesced from transposed scratch)
#pragma unroll 4
    for (int i = tid; i < GG * (B_ROWSB / 4); i += B_THREADS) {
        int k = i & 15, g = i >> 4;   // 16 float4 per gene row
        *(float4*)(gls + g * B_ROWSB + 4 * k) =
            *(const float4*)(g_glT + (size_t)g * BB + b0 + 4 * k);
    }
#pragma unroll 4
    for (int i = tid; i < GG * PHP; i += B_THREADS) {
        int g = i >> 7, j = i & (PHP - 1);
        sWp1[i] = (j < PHH) ? Wp1[g * PHH + j] : 0.f;
    }
    if (tid < PHP) {
        sbp1[tid] = (tid < PHH) ? bp1[tid] : 0.f;
        sWp2[tid] = (tid < PHH) ? Wp2[tid] : 0.f;
    }
    __syncthreads();

    const int row  = tid & 31;        // rows: row, row+32
    const int jsub = tid >> 5;        // warp-uniform: 8 subsets x 16 j
    const int jb   = jsub * 16;

    unsigned long long acc0[8], acc1[8];
#pragma unroll
    for (int c = 0; c < 8; c++) { acc0[c] = 0ull; acc1[c] = 0ull; }

#pragma unroll 4
    for (int g = 0; g < GG; g++) {
        const float* gr = gls + g * B_ROWSB + row;
        unsigned long long x0 = f2dup(gr[0]);
        unsigned long long x1 = f2dup(gr[32]);
        const ulonglong2* wp = (const ulonglong2*)(sWp1 + g * PHP + jb);
#pragma unroll
        for (int p = 0; p < 4; p++) {
            ulonglong2 w = wp[p];
            acc0[2 * p]     = f2fma(x0, w.x, acc0[2 * p]);
            acc1[2 * p]     = f2fma(x1, w.x, acc1[2 * p]);
            acc0[2 * p + 1] = f2fma(x0, w.y, acc0[2 * p + 1]);
            acc1[2 * p + 1] = f2fma(x1, w.y, acc1[2 * p + 1]);
        }
    }

    float o0 = 0.f, o1 = 0.f;
#pragma unroll
    for (int c = 0; c < 8; c++) {
        int j0 = jb + 2 * c, j1 = j0 + 1;
        float p00 = fmaxf(f2lo(acc0[c]) + sbp1[j0], 0.f);
        float p01 = fmaxf(f2hi(acc0[c]) + sbp1[j1], 0.f);
        float p10 = fmaxf(f2lo(acc1[c]) + sbp1[j0], 0.f);
        float p11 = fmaxf(f2hi(acc1[c]) + sbp1[j1], 0.f);
        o0 = fmaf(p00, sWp2[j0], o0);
        o0 = fmaf(p01, sWp2[j1], o0);
        o1 = fmaf(p10, sWp2[j0], o1);
        o1 = fmaf(p11, sWp2[j1], o1);
    }
    op[jsub * B_ROWSB + row]      = o0;
    op[jsub * B_ROWSB + row + 32] = o1;
    __syncthreads();

    if (tid < B_ROWSB) {
        float v = bp2[0];
#pragma unroll
        for (int c = 0; c < 8; c++) v += op[c * B_ROWSB + tid];
        out[b0 + tid] = v;
    }
}

// ---------------------------------------------------------------------------
extern "C" void kernel_launch(void* const* d_in, const int* in_sizes, int n_in,
                              void* d_out, int out_size) {
    const float* x   = (const float*)d_in[0];
    const float* W1  = (const float*)d_in[1];
    const float* b1  = (const float*)d_in[2];
    const float* W2  = (const float*)d_in[3];
    const float* b2  = (const float*)d_in[4];
    const float* Wp1 = (const float*)d_in[5];
    const float* bp1 = (const float*)d_in[6];
    const float* Wp2 = (const float*)d_in[7];
    const float* bp2 = (const float*)d_in[8];
    float* out = (float*)d_out;

    cudaFuncSetAttribute(kernelA, cudaFuncAttributeMaxDynamicSharedMemorySize,
                         A_SMEM_BYTES);
    cudaFuncSetAttribute(kernelB, cudaFuncAttributeMaxDynamicSharedMemorySize,
                         B_SMEM_BYTES);

    // single launch: one wave-tail instead of four, no inter-launch gaps
    dim3 gridA(GG, BB / AR);
    kernelA<<<gridA, ATH, A_SMEM_BYTES>>>(x, W1, b1, W2, b2);

    dim3 gridB(BB / B_ROWSB);
    kernelB<<<gridB, B_THREADS, B_SMEM_BYTES>>>(Wp1, bp1, Wp2, bp2, out);
}